// round 12
// baseline (speedup 1.0000x reference)
#include <cuda_runtime.h>

#define BB 65536
#define DD 8
#define HH 128
#define EE 64

typedef unsigned long long ull;

__device__ __forceinline__ ull ffma2(ull a, ull b, ull c) {
    ull d;
    asm("fma.rn.f32x2 %0,%1,%2,%3;" : "=l"(d) : "l"(a), "l"(b), "l"(c));
    return d;
}
__device__ __forceinline__ ull pk2(float lo, float hi) {
    ull r;
    asm("mov.b64 %0,{%1,%2};" : "=l"(r) : "f"(lo), "f"(hi));
    return r;
}
__device__ __forceinline__ float2 upk(ull v) {
    float2 r;
    asm("mov.b64 {%0,%1},%2;" : "=f"(r.x), "=f"(r.y) : "l"(v));
    return r;
}
__device__ __forceinline__ ulonglong2 ld4(const float* p) {
    return *(const ulonglong2*)p;
}
__device__ __forceinline__ void cpa16(float* sdst, const float* gsrc) {
    unsigned sa = (unsigned)__cvta_generic_to_shared(sdst);
    asm volatile("cp.async.cg.shared.global [%0], [%1], 16;" :: "r"(sa), "l"(gsrc));
}
#define CP_COMMIT() asm volatile("cp.async.commit_group;" ::: "memory")
#define CP_WAIT1()  asm volatile("cp.async.wait_group 1;" ::: "memory")

// FFMA-only sin: reduce to [-pi,pi], degree-11 odd minimax.
__device__ __forceinline__ float fast_sin(float x) {
    float k = rintf(x * 0.15915494309f);
    float r = fmaf(k, -6.2831855f, x);
    r = fmaf(k, 1.7484555e-7f, r);
    float r2 = r * r;
    float p = -2.3889859e-8f;
    p = fmaf(p, r2, 2.7525562e-6f);
    p = fmaf(p, r2, -1.9840874e-4f);
    p = fmaf(p, r2, 8.3333310e-3f);
    p = fmaf(p, r2, -1.6666667e-1f);
    p = fmaf(p, r2, 1.0f);
    return r * p;
}

// ---------------- scratch ---------------------------------------------------
__device__ float g_tok[BB * DD * EE];   // [b][token d][o]
__device__ float g_S[BB];               // folded scalar accumulator

// ============================================================================
// Kernel A: tokens = W3 sin(W2 sin(x*w1+b1)+b2)+b3
// 1024 threads (32 warps/SM), tile 2 rows per thread.
// ============================================================================
#define ST 132
#define TOK_SMEM_F (320*ST + 128*3 + 64 + 64)   // 42752

__global__ __launch_bounds__(1024, 1)
void tok_kernel(const float* __restrict__ x,
                const float* __restrict__ w1, const float* __restrict__ b1,
                const float* __restrict__ w2, const float* __restrict__ b2,
                const float* __restrict__ w3, const float* __restrict__ b3)
{
    extern __shared__ float sm[];
    float* sW2  = sm;                    // [k][h] native, stride 132
    float* sW3  = sW2 + 128 * ST;
    float* sh1  = sW3 + 64 * ST;
    float* sh2  = sh1 + 64 * ST;
    float* sw1c = sh2 + 64 * ST;
    float* sb1c = sw1c + 128;
    float* sb2c = sb1c + 128;
    float* sb3c = sb2c + 128;
    float* sx   = sb3c + 64;

    const int d    = blockIdx.y;
    const int tid  = threadIdx.x;
    const int w    = tid >> 5, lane = tid & 31;
    const int kl   = lane & 15, sg = lane >> 4;
    const int eh   = w & 1;              // output half
    const int rgw  = w >> 1;             // 0..15
    const int tr0  = rgw * 4 + sg * 2;   // this thread's 2 rows

    for (int i = tid; i < HH * HH; i += 1024) {
        int k = i >> 7, h = i & 127;
        sW2[k * ST + h] = w2[d * HH * HH + i];
    }
    for (int i = tid; i < EE * HH; i += 1024) {
        int o = i >> 7, h = i & 127;
        sW3[o * ST + h] = w3[d * EE * HH + i];
    }
    if (tid < 128) {
        sw1c[tid] = w1[d * HH + tid];
        sb1c[tid] = b1[d * HH + tid];
        sb2c[tid] = b2[d * HH + tid];
    }
    if (tid < 64) sb3c[tid] = b3[d * EE + tid];

    for (int t = blockIdx.x; t < BB / 64; t += gridDim.x) {
        const int r0 = t * 64;
        __syncthreads();
        if (tid < 64) sx[tid] = x[(r0 + tid) * DD + d];
        __syncthreads();

        for (int i = tid; i < 64 * HH; i += 1024) {
            int r = i >> 7, h = i & 127;
            sh1[r * ST + h] = fast_sin(fmaf(sx[r], sw1c[h], sb1c[h]));
        }
        __syncthreads();

        // GEMM1: thread = 2 rows x 4 outs
        {
            ull acc[2][4];
            #pragma unroll
            for (int i = 0; i < 2; i++)
                #pragma unroll
                for (int s = 0; s < 4; s++) acc[i][s] = 0ull;

            const float* bp = sW2 + (kl + 64 * eh) * ST;
            const float* a0 = sh1 + tr0 * ST;
            #pragma unroll 4
            for (int h = 0; h < HH; h += 4) {
                ulonglong2 bv[4];
                #pragma unroll
                for (int s = 0; s < 4; s++) bv[s] = ld4(bp + s * 16 * ST + h);
                ulonglong2 av0 = ld4(a0 + h);
                ulonglong2 av1 = ld4(a0 + ST + h);
                #pragma unroll
                for (int s = 0; s < 4; s++) {
                    acc[0][s] = ffma2(av0.x, bv[s].x, acc[0][s]);
                    acc[0][s] = ffma2(av0.y, bv[s].y, acc[0][s]);
                    acc[1][s] = ffma2(av1.x, bv[s].x, acc[1][s]);
                    acc[1][s] = ffma2(av1.y, bv[s].y, acc[1][s]);
                }
            }
            #pragma unroll
            for (int i = 0; i < 2; i++)
                #pragma unroll
                for (int s = 0; s < 4; s++) {
                    float2 p = upk(acc[i][s]);
                    int k = kl + 16 * s + 64 * eh;
                    sh2[(tr0 + i) * ST + k] = fast_sin(p.x + p.y + sb2c[k]);
                }
        }
        __syncthreads();

        // GEMM2: thread = 2 rows x 2 outs
        {
            ull acc[2][2];
            #pragma unroll
            for (int i = 0; i < 2; i++)
                #pragma unroll
                for (int s = 0; s < 2; s++)
                    acc[i][s] = pk2(sb3c[kl + 16 * s + 32 * eh], 0.f);

            const float* bp = sW3 + (kl + 32 * eh) * ST;
            const float* a0 = sh2 + tr0 * ST;
            #pragma unroll 4
            for (int h = 0; h < HH; h += 4) {
                ulonglong2 bv[2];
                #pragma unroll
                for (int s = 0; s < 2; s++) bv[s] = ld4(bp + s * 16 * ST + h);
                ulonglong2 av0 = ld4(a0 + h);
                ulonglong2 av1 = ld4(a0 + ST + h);
                #pragma unroll
                for (int s = 0; s < 2; s++) {
                    acc[0][s] = ffma2(av0.x, bv[s].x, acc[0][s]);
                    acc[0][s] = ffma2(av0.y, bv[s].y, acc[0][s]);
                    acc[1][s] = ffma2(av1.x, bv[s].x, acc[1][s]);
                    acc[1][s] = ffma2(av1.y, bv[s].y, acc[1][s]);
                }
            }
            #pragma unroll
            for (int i = 0; i < 2; i++)
                #pragma unroll
                for (int s = 0; s < 2; s++) {
                    float2 p = upk(acc[i][s]);
                    int e = kl + 16 * s + 32 * eh;
                    g_tok[((r0 + tr0 + i) * DD + d) * EE + e] = p.x + p.y;
                }
        }
    }
}

// ============================================================================
// MHA (folded): tile 8 rows, cp.async double-buffered staging, shuffle pooling.
// (unchanged from R11)
// ============================================================================
#define SW 68
#define SWT 68
#define SMH 68
#define MHA_PREFIX_F (128*SW + 128 + 4*SMH + 64 + 8 + 2*32*SW)   // 13528
#define MHA_SELF_F  (MHA_PREFIX_F + 2*32*SWT)   // 17880 (71.5 KB)
#define MHA_CROSS_F (MHA_PREFIX_F + 2*64*SWT)   // 22232 (88.9 KB)

template<int QOFF, int KVOFF, bool ACCUM, bool POOLB>
__global__ __launch_bounds__(256, 2)
void mha_kernel(const float* __restrict__ Win, const float* __restrict__ bin,
                const float* __restrict__ Wo,  const float* __restrict__ Wf)
{
    extern __shared__ float sm_[];
    float* sWqk  = sm_;                  // [e][c] e<64: Wq, e>=64: Wk
    float* sbqk  = sWqk + 128 * SW;      // 128
    float* smh   = sbqk + 128;           // [h][c]
    float* su    = smh + 4 * SMH;        // 64
    float* scb   = su + 64;              // 8
    float* sq    = scb + 8;              // [tr][68] (32 token-rows)
    float* sk    = sq + 32 * SW;
    float* stokA = sk + 32 * SW;         // buffer 0
    constexpr int SROWS = (QOFF == KVOFF) ? 32 : 64;
    float* stokB = stokA + SROWS * SWT;  // buffer 1

    const int tid  = threadIdx.x;
    const int w    = tid >> 5, lane = tid & 31;
    const int kl   = lane & 15, sg = lane >> 4;
    const int eh   = w & 1;              // 0 = Q, 1 = K
    const int rgw  = w >> 1;
    const int tr0  = rgw * 8 + sg * 4;

    constexpr bool SELF = (QOFF == KVOFF);
    constexpr int FOFF = POOLB ? 64 : 0;
    const int NT = BB / 8;

    for (int i = tid; i < 128 * 64; i += 256) {
        int e = i >> 6, c = i & 63;
        sWqk[e * SW + c] = Win[i];
    }
    if (tid < 128) sbqk[tid] = bin[tid];

    if (tid < 64) {
        float s = 0.f;
        for (int e = 0; e < 64; e++) s = fmaf(Wf[FOFF + e], Wo[e * 64 + tid], s);
        su[tid] = s;
    }
    __syncthreads();

    {
        int h = tid >> 6, dd2 = tid & 63;
        float s = 0.f;
        #pragma unroll
        for (int cc = 0; cc < 16; cc++)
            s = fmaf(su[h * 16 + cc], Win[(128 + h * 16 + cc) * 64 + dd2], s);
        smh[h * SMH + dd2] = s;
    }
    if (tid == 0) {
        float s = 0.f;
        for (int c = 0; c < 64; c++) s = fmaf(su[c], bin[128 + c], s);
        scb[0] = 0.5f * s;
    }

    auto issue = [&](int t, float* buf) {
        const int r0 = t * 8;
        if (SELF) {
            #pragma unroll
            for (int i2 = 0; i2 < 2; i2++) {
                int i = tid + 256 * i2;
                int trow = i >> 4, c4 = i & 15;
                int br = trow >> 2, tk = trow & 3;
                cpa16(buf + trow * SWT + c4 * 4,
                      g_tok + (r0 + br) * 512 + (QOFF + tk) * 64 + c4 * 4);
            }
        } else {
            #pragma unroll
            for (int i2 = 0; i2 < 4; i2++) {
                int i = tid + 256 * i2;
                int trow = i >> 4, c4 = i & 15;
                cpa16(buf + trow * SWT + c4 * 4, g_tok + r0 * 512 + i * 4);
            }
        }
    };

    if (blockIdx.x < NT) issue(blockIdx.x, stokA);
    CP_COMMIT();

    int parity = 0;
    for (int t = blockIdx.x; t < NT; t += gridDim.x) {
        const int r0 = t * 8;
        float* cur = parity ? stokB : stokA;
        float* nxt = parity ? stokA : stokB;

        __syncthreads();
        int tn = t + gridDim.x;
        if (tn < NT) issue(tn, nxt);
        CP_COMMIT();
        CP_WAIT1();
        __syncthreads();

        // ---- Q/K proj: thread = 4 token-rows x 4 outputs ------------------
        {
            ull acc[4][4];
            #pragma unroll
            for (int i = 0; i < 4; i++)
                #pragma unroll
                for (int s = 0; s < 4; s++)
                    acc[i][s] = pk2(sbqk[kl + 16 * s + 64 * eh], 0.f);

            const int off = eh ? KVOFF : QOFF;
            const float* ap[4];
            #pragma unroll
            for (int i = 0; i < 4; i++) {
                int tr = tr0 + i;
                int row;
                if (SELF) row = tr;
                else      row = (tr >> 2) * 8 + off + (tr & 3);
                ap[i] = cur + row * SWT;
            }
            const float* bp = sWqk + (kl + 64 * eh) * SW;

            #pragma unroll 2
            for (int c = 0; c < 64; c += 4) {
                ulonglong2 bv[4];
                #pragma unroll
                for (int s = 0; s < 4; s++) bv[s] = ld4(bp + s * 16 * SW + c);
                #pragma unroll
                for (int i = 0; i < 4; i++) {
                    ulonglong2 av = ld4(ap[i] + c);
                    #pragma unroll
                    for (int s = 0; s < 4; s++) {
                        acc[i][s] = ffma2(av.x, bv[s].x, acc[i][s]);
                        acc[i][s] = ffma2(av.y, bv[s].y, acc[i][s]);
                    }
                }
            }
            float* dest = eh ? sk : sq;
            #pragma unroll
            for (int i = 0; i < 4; i++) {
                int trw = (tr0 + i) * SW;
                #pragma unroll
                for (int s = 0; s < 4; s++) {
                    float2 p = upk(acc[i][s]);
                    dest[trw + kl + 16 * s] = p.x + p.y;
                }
            }
        }
        __syncthreads();

        // ---- attention + folded pooling: warp w -> batch row w ------------
        {
            const int br = w;
            const float* sq_r = sq + br * 4 * SW;
            const float* sk_r = sk + br * 4 * SW;

            float a01[2];
            #pragma unroll
            for (int z = 0; z < 2; z++) {
                int m = lane + 32 * z;
                int h = m >> 4, i = (m >> 2) & 3, j = m & 3;
                const float* qb = sq_r + i * SW + h * 16;
                const float* kb = sk_r + j * SW + h * 16;
                ull acc = 0ull;
                #pragma unroll
                for (int dd2 = 0; dd2 < 16; dd2 += 4) {
                    ulonglong2 qv = ld4(qb + dd2);
                    ulonglong2 kv = ld4(kb + dd2);
                    acc = ffma2(qv.x, kv.x, acc);
                    acc = ffma2(qv.y, kv.y, acc);
                }
                float2 p = upk(acc);
                a01[z] = (p.x + p.y) * 0.25f;
            }
            float m0 = a01[0], m1 = a01[1];
            m0 = fmaxf(m0, __shfl_xor_sync(0xffffffffu, m0, 1));
            m0 = fmaxf(m0, __shfl_xor_sync(0xffffffffu, m0, 2));
            m1 = fmaxf(m1, __shfl_xor_sync(0xffffffffu, m1, 1));
            m1 = fmaxf(m1, __shfl_xor_sync(0xffffffffu, m1, 2));
            float e0 = __expf(a01[0] - m0), e1 = __expf(a01[1] - m1);
            float s0 = e0, s1 = e1;
            s0 += __shfl_xor_sync(0xffffffffu, s0, 1);
            s0 += __shfl_xor_sync(0xffffffffu, s0, 2);
            s1 += __shfl_xor_sync(0xffffffffu, s1, 1);
            s1 += __shfl_xor_sync(0xffffffffu, s1, 2);
            float p0 = __fdividef(e0, s0);
            float p1 = __fdividef(e1, s1);

            float w0 = p0 + __shfl_xor_sync(0xffffffffu, p0, 4);
            w0 += __shfl_xor_sync(0xffffffffu, w0, 8);
            float w1 = p1 + __shfl_xor_sync(0xffffffffu, p1, 4);
            w1 += __shfl_xor_sync(0xffffffffu, w1, 8);

            int h = lane >> 2, j = lane & 3;
            int src = (h & 1) * 16 + j;
            float wa  = __shfl_sync(0xffffffffu, w0, src);
            float wbv = __shfl_sync(0xffffffffu, w1, src);
            float wbar = (h < 2) ? wa : wbv;

            float part = 0.f;
            {
                int kvrow = SELF ? (br * 4 + j) : (br * 8 + KVOFF + j);
                const float* mh = smh + h * SMH;
                const float* tj = cur + kvrow * SWT;
                ull acc = 0ull;
                #pragma unroll
                for (int c = 0; c < 64; c += 4) {
                    ulonglong2 mv = ld4(mh + c);
                    ulonglong2 tv = ld4(tj + c);
                    acc = ffma2(mv.x, tv.x, acc);
                    acc = ffma2(mv.y, tv.y, acc);
                }
                float2 p = upk(acc);
                part = wbar * (p.x + p.y);
                if (lane >= 16) part = 0.f;
            }
            part += __shfl_down_sync(0xffffffffu, part, 8);
            part += __shfl_down_sync(0xffffffffu, part, 4);
            part += __shfl_down_sync(0xffffffffu, part, 2);
            part += __shfl_down_sync(0xffffffffu, part, 1);
            if (lane == 0) {
                float S = 0.125f * part + scb[0];
                if (ACCUM) g_S[r0 + br] += S;
                else       g_S[r0 + br]  = S;
            }
        }
        parity ^= 1;
    }
}

// ---------------- epilogue: out = leaky(S + C) ------------------------------
__global__ __launch_bounds__(256)
void epi_kernel(const float* __restrict__ Wf, const float* __restrict__ bf,
                const float* __restrict__ bo_sa, const float* __restrict__ bo_sb,
                const float* __restrict__ bo_ca, const float* __restrict__ bo_cb,
                float* __restrict__ out)
{
    int b = blockIdx.x * blockDim.x + threadIdx.x;
    if (b >= BB) return;
    float C = bf[0];
    #pragma unroll 4
    for (int e = 0; e < 64; e++) {
        C = fmaf(0.5f * Wf[e],      bo_sa[e] + bo_ca[e], C);
        C = fmaf(0.5f * Wf[64 + e], bo_sb[e] + bo_cb[e], C);
    }
    float s = g_S[b] + C;
    out[b] = (s > 0.f) ? s : 0.01f * s;
}

// ---------------- launch ----------------------------------------------------
static const int A_SMEM   = TOK_SMEM_F * 4;
static const int M_SMEM_S = MHA_SELF_F * 4;
static const int M_SMEM_C = MHA_CROSS_F * 4;

extern "C" void kernel_launch(void* const* d_in, const int* in_sizes, int n_in,
                              void* d_out, int out_size)
{
    (void)in_sizes; (void)n_in; (void)out_size;
    const float* x  = (const float*)d_in[0];
    const float* w1 = (const float*)d_in[1];
    const float* b1 = (const float*)d_in[2];
    const float* w2 = (const float*)d_in[3];
    const float* b2 = (const float*)d_in[4];
    const float* w3 = (const float*)d_in[5];
    const float* b3 = (const float*)d_in[6];
    const float* Win_sa = (const float*)d_in[7];
    const float* bin_sa = (const float*)d_in[8];
    const float* Wo_sa  = (const float*)d_in[9];
    const float* bo_sa  = (const float*)d_in[10];
    const float* Win_sb = (const float*)d_in[11];
    const float* bin_sb = (const float*)d_in[12];
    const float* Wo_sb  = (const float*)d_in[13];
    const float* bo_sb  = (const float*)d_in[14];
    const float* Win_ca = (const float*)d_in[15];
    const float* bin_ca = (const float*)d_in[16];
    const float* Wo_ca  = (const float*)d_in[17];
    const float* bo_ca  = (const float*)d_in[18];
    const float* Win_cb = (const float*)d_in[19];
    const float* bin_cb = (const float*)d_in[20];
    const float* Wo_cb  = (const float*)d_in[21];
    const float* bo_cb  = (const float*)d_in[22];
    const float* Wf = (const float*)d_in[23];
    const float* bf = (const float*)d_in[24];
    float* out = (float*)d_out;

    cudaFuncSetAttribute(tok_kernel, cudaFuncAttributeMaxDynamicSharedMemorySize, A_SMEM);
    cudaFuncSetAttribute(mha_kernel<0, 0, false, false>, cudaFuncAttributeMaxDynamicSharedMemorySize, M_SMEM_S);
    cudaFuncSetAttribute(mha_kernel<4, 4, true,  true>,  cudaFuncAttributeMaxDynamicSharedMemorySize, M_SMEM_S);
    cudaFuncSetAttribute(mha_kernel<0, 4, true,  false>, cudaFuncAttributeMaxDynamicSharedMemorySize, M_SMEM_C);
    cudaFuncSetAttribute(mha_kernel<4, 0, true,  true>,  cudaFuncAttributeMaxDynamicSharedMemorySize, M_SMEM_C);

    tok_kernel<<<dim3(18, 8), 1024, A_SMEM>>>(x, w1, b1, w2, b2, w3, b3);

    mha_kernel<0, 0, false, false><<<296, 256, M_SMEM_S>>>(Win_sa, bin_sa, Wo_sa, Wf);
    mha_kernel<4, 4, true,  true ><<<296, 256, M_SMEM_S>>>(Win_sb, bin_sb, Wo_sb, Wf);
    mha_kernel<0, 4, true,  false><<<296, 256, M_SMEM_C>>>(Win_ca, bin_ca, Wo_ca, Wf);
    mha_kernel<4, 0, true,  true ><<<296, 256, M_SMEM_C>>>(Win_cb, bin_cb, Wo_cb, Wf);

    epi_kernel<<<BB / 256, 256>>>(Wf, bf, bo_sa, bo_sb, bo_ca, bo_cb, out);
}

// round 13
// speedup vs baseline: 1.2509x; 1.2509x over previous
#include <cuda_runtime.h>

#define BB 65536
#define DD 8
#define HH 128
#define EE 64

typedef unsigned long long ull;

__device__ __forceinline__ ull ffma2(ull a, ull b, ull c) {
    ull d;
    asm("fma.rn.f32x2 %0,%1,%2,%3;" : "=l"(d) : "l"(a), "l"(b), "l"(c));
    return d;
}
__device__ __forceinline__ ull pk2(float lo, float hi) {
    ull r;
    asm("mov.b64 %0,{%1,%2};" : "=l"(r) : "f"(lo), "f"(hi));
    return r;
}
__device__ __forceinline__ float2 upk(ull v) {
    float2 r;
    asm("mov.b64 {%0,%1},%2;" : "=f"(r.x), "=f"(r.y) : "l"(v));
    return r;
}
__device__ __forceinline__ ulonglong2 ld4(const float* p) {
    return *(const ulonglong2*)p;
}
__device__ __forceinline__ void cpa16(float* sdst, const float* gsrc) {
    unsigned sa = (unsigned)__cvta_generic_to_shared(sdst);
    asm volatile("cp.async.cg.shared.global [%0], [%1], 16;" :: "r"(sa), "l"(gsrc));
}
#define CP_COMMIT() asm volatile("cp.async.commit_group;" ::: "memory")
#define CP_WAIT1()  asm volatile("cp.async.wait_group 1;" ::: "memory")

// ---------------- scratch ---------------------------------------------------
__device__ float g_tok[BB * DD * EE];   // [b][token d][o]
__device__ float g_S[BB];               // folded scalar accumulator

// ============================================================================
// Kernel A: tokens = W3 sin(W2 sin(x*w1+b1)+b2)+b3
// R11 shape (512 threads, 4-row tile); sins on MUFU via __sinf.
// ============================================================================
#define ST 132
#define TOK_SMEM_F (320*ST + 128*3 + 64 + 64)   // 42752

__global__ __launch_bounds__(512, 1)
void tok_kernel(const float* __restrict__ x,
                const float* __restrict__ w1, const float* __restrict__ b1,
                const float* __restrict__ w2, const float* __restrict__ b2,
                const float* __restrict__ w3, const float* __restrict__ b3)
{
    extern __shared__ float sm[];
    float* sW2  = sm;                    // [k][h] native, stride 132
    float* sW3  = sW2 + 128 * ST;
    float* sh1  = sW3 + 64 * ST;
    float* sh2  = sh1 + 64 * ST;
    float* sw1c = sh2 + 64 * ST;
    float* sb1c = sw1c + 128;
    float* sb2c = sb1c + 128;
    float* sb3c = sb2c + 128;
    float* sx   = sb3c + 64;

    const int d    = blockIdx.y;
    const int tid  = threadIdx.x;
    const int w    = tid >> 5, lane = tid & 31;
    const int kl   = lane & 15, sg = lane >> 4;
    const int eh   = w & 1;
    const int rgw  = w >> 1;
    const int tr0  = rgw * 8 + sg * 4;

    for (int i = tid; i < HH * HH; i += 512) {
        int k = i >> 7, h = i & 127;
        sW2[k * ST + h] = w2[d * HH * HH + i];
    }
    for (int i = tid; i < EE * HH; i += 512) {
        int o = i >> 7, h = i & 127;
        sW3[o * ST + h] = w3[d * EE * HH + i];
    }
    if (tid < 128) {
        sw1c[tid] = w1[d * HH + tid];
        sb1c[tid] = b1[d * HH + tid];
        sb2c[tid] = b2[d * HH + tid];
    }
    if (tid < 64) sb3c[tid] = b3[d * EE + tid];

    for (int t = blockIdx.x; t < BB / 64; t += gridDim.x) {
        const int r0 = t * 64;
        __syncthreads();
        if (tid < 64) sx[tid] = x[(r0 + tid) * DD + d];
        __syncthreads();

        for (int i = tid; i < 64 * HH; i += 512) {
            int r = i >> 7, h = i & 127;
            sh1[r * ST + h] = __sinf(fmaf(sx[r], sw1c[h], sb1c[h]));
        }
        __syncthreads();

        // GEMM1: thread = 4 rows x 4 outs
        {
            ull acc[4][4];
            #pragma unroll
            for (int i = 0; i < 4; i++)
                #pragma unroll
                for (int s = 0; s < 4; s++) acc[i][s] = 0ull;

            const float* bp = sW2 + (kl + 64 * eh) * ST;
            const float* a0 = sh1 + tr0 * ST;
            #pragma unroll 2
            for (int h = 0; h < HH; h += 4) {
                ulonglong2 bv[4];
                #pragma unroll
                for (int s = 0; s < 4; s++) bv[s] = ld4(bp + s * 16 * ST + h);
                #pragma unroll
                for (int i = 0; i < 4; i++) {
                    ulonglong2 av = ld4(a0 + i * ST + h);
                    #pragma unroll
                    for (int s = 0; s < 4; s++) {
                        acc[i][s] = ffma2(av.x, bv[s].x, acc[i][s]);
                        acc[i][s] = ffma2(av.y, bv[s].y, acc[i][s]);
                    }
                }
            }
            #pragma unroll
            for (int i = 0; i < 4; i++)
                #pragma unroll
                for (int s = 0; s < 4; s++) {
                    float2 p = upk(acc[i][s]);
                    int k = kl + 16 * s + 64 * eh;
                    sh2[(tr0 + i) * ST + k] = __sinf(p.x + p.y + sb2c[k]);
                }
        }
        __syncthreads();

        // GEMM2: thread = 4 rows x 2 outs
        {
            ull acc[4][2];
            #pragma unroll
            for (int i = 0; i < 4; i++)
                #pragma unroll
                for (int s = 0; s < 2; s++)
                    acc[i][s] = pk2(sb3c[kl + 16 * s + 32 * eh], 0.f);

            const float* bp = sW3 + (kl + 32 * eh) * ST;
            const float* a0 = sh2 + tr0 * ST;
            #pragma unroll 2
            for (int h = 0; h < HH; h += 4) {
                ulonglong2 bv[2];
                #pragma unroll
                for (int s = 0; s < 2; s++) bv[s] = ld4(bp + s * 16 * ST + h);
                #pragma unroll
                for (int i = 0; i < 4; i++) {
                    ulonglong2 av = ld4(a0 + i * ST + h);
                    #pragma unroll
                    for (int s = 0; s < 2; s++) {
                        acc[i][s] = ffma2(av.x, bv[s].x, acc[i][s]);
                        acc[i][s] = ffma2(av.y, bv[s].y, acc[i][s]);
                    }
                }
            }
            #pragma unroll
            for (int i = 0; i < 4; i++)
                #pragma unroll
                for (int s = 0; s < 2; s++) {
                    float2 p = upk(acc[i][s]);
                    int e = kl + 16 * s + 32 * eh;
                    g_tok[((r0 + tr0 + i) * DD + d) * EE + e] = p.x + p.y;
                }
        }
    }
}

// ============================================================================
// MHA (folded): tile 8 rows, cp.async double-buffered staging, shuffle pooling.
// (byte-identical to R11)
// ============================================================================
#define SW 68
#define SWT 68
#define SMH 68
#define MHA_PREFIX_F (128*SW + 128 + 4*SMH + 64 + 8 + 2*32*SW)   // 13528
#define MHA_SELF_F  (MHA_PREFIX_F + 2*32*SWT)   // 17880 (71.5 KB)
#define MHA_CROSS_F (MHA_PREFIX_F + 2*64*SWT)   // 22232 (88.9 KB)

template<int QOFF, int KVOFF, bool ACCUM, bool POOLB>
__global__ __launch_bounds__(256, 2)
void mha_kernel(const float* __restrict__ Win, const float* __restrict__ bin,
                const float* __restrict__ Wo,  const float* __restrict__ Wf)
{
    extern __shared__ float sm_[];
    float* sWqk  = sm_;                  // [e][c] e<64: Wq, e>=64: Wk
    float* sbqk  = sWqk + 128 * SW;      // 128
    float* smh   = sbqk + 128;           // [h][c]
    float* su    = smh + 4 * SMH;        // 64
    float* scb   = su + 64;              // 8
    float* sq    = scb + 8;              // [tr][68] (32 token-rows)
    float* sk    = sq + 32 * SW;
    float* stokA = sk + 32 * SW;         // buffer 0
    constexpr int SROWS = (QOFF == KVOFF) ? 32 : 64;
    float* stokB = stokA + SROWS * SWT;  // buffer 1

    const int tid  = threadIdx.x;
    const int w    = tid >> 5, lane = tid & 31;
    const int kl   = lane & 15, sg = lane >> 4;
    const int eh   = w & 1;              // 0 = Q, 1 = K
    const int rgw  = w >> 1;
    const int tr0  = rgw * 8 + sg * 4;

    constexpr bool SELF = (QOFF == KVOFF);
    constexpr int FOFF = POOLB ? 64 : 0;
    const int NT = BB / 8;

    for (int i = tid; i < 128 * 64; i += 256) {
        int e = i >> 6, c = i & 63;
        sWqk[e * SW + c] = Win[i];
    }
    if (tid < 128) sbqk[tid] = bin[tid];

    if (tid < 64) {
        float s = 0.f;
        for (int e = 0; e < 64; e++) s = fmaf(Wf[FOFF + e], Wo[e * 64 + tid], s);
        su[tid] = s;
    }
    __syncthreads();

    {
        int h = tid >> 6, dd2 = tid & 63;
        float s = 0.f;
        #pragma unroll
        for (int cc = 0; cc < 16; cc++)
            s = fmaf(su[h * 16 + cc], Win[(128 + h * 16 + cc) * 64 + dd2], s);
        smh[h * SMH + dd2] = s;
    }
    if (tid == 0) {
        float s = 0.f;
        for (int c = 0; c < 64; c++) s = fmaf(su[c], bin[128 + c], s);
        scb[0] = 0.5f * s;
    }

    auto issue = [&](int t, float* buf) {
        const int r0 = t * 8;
        if (SELF) {
            #pragma unroll
            for (int i2 = 0; i2 < 2; i2++) {
                int i = tid + 256 * i2;
                int trow = i >> 4, c4 = i & 15;
                int br = trow >> 2, tk = trow & 3;
                cpa16(buf + trow * SWT + c4 * 4,
                      g_tok + (r0 + br) * 512 + (QOFF + tk) * 64 + c4 * 4);
            }
        } else {
            #pragma unroll
            for (int i2 = 0; i2 < 4; i2++) {
                int i = tid + 256 * i2;
                int trow = i >> 4, c4 = i & 15;
                cpa16(buf + trow * SWT + c4 * 4, g_tok + r0 * 512 + i * 4);
            }
        }
    };

    if (blockIdx.x < NT) issue(blockIdx.x, stokA);
    CP_COMMIT();

    int parity = 0;
    for (int t = blockIdx.x; t < NT; t += gridDim.x) {
        const int r0 = t * 8;
        float* cur = parity ? stokB : stokA;
        float* nxt = parity ? stokA : stokB;

        __syncthreads();
        int tn = t + gridDim.x;
        if (tn < NT) issue(tn, nxt);
        CP_COMMIT();
        CP_WAIT1();
        __syncthreads();

        // ---- Q/K proj: thread = 4 token-rows x 4 outputs ------------------
        {
            ull acc[4][4];
            #pragma unroll
            for (int i = 0; i < 4; i++)
                #pragma unroll
                for (int s = 0; s < 4; s++)
                    acc[i][s] = pk2(sbqk[kl + 16 * s + 64 * eh], 0.f);

            const int off = eh ? KVOFF : QOFF;
            const float* ap[4];
            #pragma unroll
            for (int i = 0; i < 4; i++) {
                int tr = tr0 + i;
                int row;
                if (SELF) row = tr;
                else      row = (tr >> 2) * 8 + off + (tr & 3);
                ap[i] = cur + row * SWT;
            }
            const float* bp = sWqk + (kl + 64 * eh) * SW;

            #pragma unroll 2
            for (int c = 0; c < 64; c += 4) {
                ulonglong2 bv[4];
                #pragma unroll
                for (int s = 0; s < 4; s++) bv[s] = ld4(bp + s * 16 * SW + c);
                #pragma unroll
                for (int i = 0; i < 4; i++) {
                    ulonglong2 av = ld4(ap[i] + c);
                    #pragma unroll
                    for (int s = 0; s < 4; s++) {
                        acc[i][s] = ffma2(av.x, bv[s].x, acc[i][s]);
                        acc[i][s] = ffma2(av.y, bv[s].y, acc[i][s]);
                    }
                }
            }
            float* dest = eh ? sk : sq;
            #pragma unroll
            for (int i = 0; i < 4; i++) {
                int trw = (tr0 + i) * SW;
                #pragma unroll
                for (int s = 0; s < 4; s++) {
                    float2 p = upk(acc[i][s]);
                    dest[trw + kl + 16 * s] = p.x + p.y;
                }
            }
        }
        __syncthreads();

        // ---- attention + folded pooling: warp w -> batch row w ------------
        {
            const int br = w;
            const float* sq_r = sq + br * 4 * SW;
            const float* sk_r = sk + br * 4 * SW;

            float a01[2];
            #pragma unroll
            for (int z = 0; z < 2; z++) {
                int m = lane + 32 * z;
                int h = m >> 4, i = (m >> 2) & 3, j = m & 3;
                const float* qb = sq_r + i * SW + h * 16;
                const float* kb = sk_r + j * SW + h * 16;
                ull acc = 0ull;
                #pragma unroll
                for (int dd2 = 0; dd2 < 16; dd2 += 4) {
                    ulonglong2 qv = ld4(qb + dd2);
                    ulonglong2 kv = ld4(kb + dd2);
                    acc = ffma2(qv.x, kv.x, acc);
                    acc = ffma2(qv.y, kv.y, acc);
                }
                float2 p = upk(acc);
                a01[z] = (p.x + p.y) * 0.25f;
            }
            float m0 = a01[0], m1 = a01[1];
            m0 = fmaxf(m0, __shfl_xor_sync(0xffffffffu, m0, 1));
            m0 = fmaxf(m0, __shfl_xor_sync(0xffffffffu, m0, 2));
            m1 = fmaxf(m1, __shfl_xor_sync(0xffffffffu, m1, 1));
            m1 = fmaxf(m1, __shfl_xor_sync(0xffffffffu, m1, 2));
            float e0 = __expf(a01[0] - m0), e1 = __expf(a01[1] - m1);
            float s0 = e0, s1 = e1;
            s0 += __shfl_xor_sync(0xffffffffu, s0, 1);
            s0 += __shfl_xor_sync(0xffffffffu, s0, 2);
            s1 += __shfl_xor_sync(0xffffffffu, s1, 1);
            s1 += __shfl_xor_sync(0xffffffffu, s1, 2);
            float p0 = __fdividef(e0, s0);
            float p1 = __fdividef(e1, s1);

            float w0 = p0 + __shfl_xor_sync(0xffffffffu, p0, 4);
            w0 += __shfl_xor_sync(0xffffffffu, w0, 8);
            float w1 = p1 + __shfl_xor_sync(0xffffffffu, p1, 4);
            w1 += __shfl_xor_sync(0xffffffffu, w1, 8);

            int h = lane >> 2, j = lane & 3;
            int src = (h & 1) * 16 + j;
            float wa  = __shfl_sync(0xffffffffu, w0, src);
            float wbv = __shfl_sync(0xffffffffu, w1, src);
            float wbar = (h < 2) ? wa : wbv;

            float part = 0.f;
            {
                int kvrow = SELF ? (br * 4 + j) : (br * 8 + KVOFF + j);
                const float* mh = smh + h * SMH;
                const float* tj = cur + kvrow * SWT;
                ull acc = 0ull;
                #pragma unroll
                for (int c = 0; c < 64; c += 4) {
                    ulonglong2 mv = ld4(mh + c);
                    ulonglong2 tv = ld4(tj + c);
                    acc = ffma2(mv.x, tv.x, acc);
                    acc = ffma2(mv.y, tv.y, acc);
                }
                float2 p = upk(acc);
                part = wbar * (p.x + p.y);
                if (lane >= 16) part = 0.f;
            }
            part += __shfl_down_sync(0xffffffffu, part, 8);
            part += __shfl_down_sync(0xffffffffu, part, 4);
            part += __shfl_down_sync(0xffffffffu, part, 2);
            part += __shfl_down_sync(0xffffffffu, part, 1);
            if (lane == 0) {
                float S = 0.125f * part + scb[0];
                if (ACCUM) g_S[r0 + br] += S;
                else       g_S[r0 + br]  = S;
            }
        }
        parity ^= 1;
    }
}

// ---------------- epilogue: out = leaky(S + C) ------------------------------
__global__ __launch_bounds__(256)
void epi_kernel(const float* __restrict__ Wf, const float* __restrict__ bf,
                const float* __restrict__ bo_sa, const float* __restrict__ bo_sb,
                const float* __restrict__ bo_ca, const float* __restrict__ bo_cb,
                float* __restrict__ out)
{
    int b = blockIdx.x * blockDim.x + threadIdx.x;
    if (b >= BB) return;
    float C = bf[0];
    #pragma unroll 4
    for (int e = 0; e < 64; e++) {
        C = fmaf(0.5f * Wf[e],      bo_sa[e] + bo_ca[e], C);
        C = fmaf(0.5f * Wf[64 + e], bo_sb[e] + bo_cb[e], C);
    }
    float s = g_S[b] + C;
    out[b] = (s > 0.f) ? s : 0.01f * s;
}

// ---------------- launch ----------------------------------------------------
static const int A_SMEM   = TOK_SMEM_F * 4;
static const int M_SMEM_S = MHA_SELF_F * 4;
static const int M_SMEM_C = MHA_CROSS_F * 4;

extern "C" void kernel_launch(void* const* d_in, const int* in_sizes, int n_in,
                              void* d_out, int out_size)
{
    (void)in_sizes; (void)n_in; (void)out_size;
    const float* x  = (const float*)d_in[0];
    const float* w1 = (const float*)d_in[1];
    const float* b1 = (const float*)d_in[2];
    const float* w2 = (const float*)d_in[3];
    const float* b2 = (const float*)d_in[4];
    const float* w3 = (const float*)d_in[5];
    const float* b3 = (const float*)d_in[6];
    const float* Win_sa = (const float*)d_in[7];
    const float* bin_sa = (const float*)d_in[8];
    const float* Wo_sa  = (const float*)d_in[9];
    const float* bo_sa  = (const float*)d_in[10];
    const float* Win_sb = (const float*)d_in[11];
    const float* bin_sb = (const float*)d_in[12];
    const float* Wo_sb  = (const float*)d_in[13];
    const float* bo_sb  = (const float*)d_in[14];
    const float* Win_ca = (const float*)d_in[15];
    const float* bin_ca = (const float*)d_in[16];
    const float* Wo_ca  = (const float*)d_in[17];
    const float* bo_ca  = (const float*)d_in[18];
    const float* Win_cb = (const float*)d_in[19];
    const float* bin_cb = (const float*)d_in[20];
    const float* Wo_cb  = (const float*)d_in[21];
    const float* bo_cb  = (const float*)d_in[22];
    const float* Wf = (const float*)d_in[23];
    const float* bf = (const float*)d_in[24];
    float* out = (float*)d_out;

    cudaFuncSetAttribute(tok_kernel, cudaFuncAttributeMaxDynamicSharedMemorySize, A_SMEM);
    cudaFuncSetAttribute(mha_kernel<0, 0, false, false>, cudaFuncAttributeMaxDynamicSharedMemorySize, M_SMEM_S);
    cudaFuncSetAttribute(mha_kernel<4, 4, true,  true>,  cudaFuncAttributeMaxDynamicSharedMemorySize, M_SMEM_S);
    cudaFuncSetAttribute(mha_kernel<0, 4, true,  false>, cudaFuncAttributeMaxDynamicSharedMemorySize, M_SMEM_C);
    cudaFuncSetAttribute(mha_kernel<4, 0, true,  true>,  cudaFuncAttributeMaxDynamicSharedMemorySize, M_SMEM_C);

    tok_kernel<<<dim3(37, 8), 512, A_SMEM>>>(x, w1, b1, w2, b2, w3, b3);

    mha_kernel<0, 0, false, false><<<296, 256, M_SMEM_S>>>(Win_sa, bin_sa, Wo_sa, Wf);
    mha_kernel<4, 4, true,  true ><<<296, 256, M_SMEM_S>>>(Win_sb, bin_sb, Wo_sb, Wf);
    mha_kernel<0, 4, true,  false><<<296, 256, M_SMEM_C>>>(Win_ca, bin_ca, Wo_ca, Wf);
    mha_kernel<4, 0, true,  true ><<<296, 256, M_SMEM_C>>>(Win_cb, bin_cb, Wo_cb, Wf);

    epi_kernel<<<BB / 256, 256>>>(Wf, bf, bo_sa, bo_sb, bo_ca, bo_cb, out);
}

// round 14
// speedup vs baseline: 1.2847x; 1.0270x over previous
#include <cuda_runtime.h>

#define BB 65536
#define DD 8
#define HH 128
#define EE 64

typedef unsigned long long ull;

__device__ __forceinline__ ull ffma2(ull a, ull b, ull c) {
    ull d;
    asm("fma.rn.f32x2 %0,%1,%2,%3;" : "=l"(d) : "l"(a), "l"(b), "l"(c));
    return d;
}
__device__ __forceinline__ ull pk2(float lo, float hi) {
    ull r;
    asm("mov.b64 %0,{%1,%2};" : "=l"(r) : "f"(lo), "f"(hi));
    return r;
}
__device__ __forceinline__ float2 upk(ull v) {
    float2 r;
    asm("mov.b64 {%0,%1},%2;" : "=f"(r.x), "=f"(r.y) : "l"(v));
    return r;
}
__device__ __forceinline__ ulonglong2 ld4(const float* p) {
    return *(const ulonglong2*)p;
}
__device__ __forceinline__ void cpa16(float* sdst, const float* gsrc) {
    unsigned sa = (unsigned)__cvta_generic_to_shared(sdst);
    asm volatile("cp.async.cg.shared.global [%0], [%1], 16;" :: "r"(sa), "l"(gsrc));
}
#define CP_COMMIT() asm volatile("cp.async.commit_group;" ::: "memory")
#define CP_WAIT1()  asm volatile("cp.async.wait_group 1;" ::: "memory")
__device__ __forceinline__ void barg(int id) {
    asm volatile("bar.sync %0, 256;" :: "r"(id) : "memory");
}

// ---------------- scratch ---------------------------------------------------
__device__ float g_tok[BB * DD * EE];   // [b][token d][o]
__device__ float g_S[BB];               // folded scalar accumulator

// ============================================================================
// Kernel A: tokens = W3 sin(W2 sin(x*w1+b1)+b2)+b3
// 512 threads = 2 independent groups of 256, each on 32-row tiles.
// ============================================================================
#define ST 132
#define TOK_SMEM_F (320*ST + 128*3 + 64 + 64)   // 42752 floats (same as R13)

__global__ __launch_bounds__(512, 1)
void tok_kernel(const float* __restrict__ x,
                const float* __restrict__ w1, const float* __restrict__ b1,
                const float* __restrict__ w2, const float* __restrict__ b2,
                const float* __restrict__ w3, const float* __restrict__ b3)
{
    extern __shared__ float sm[];
    float* sW2  = sm;                    // [k][h] native, stride 132
    float* sW3  = sW2 + 128 * ST;
    float* sh1b = sW3 + 64 * ST;         // 2 groups x 32 x ST
    float* sh2b = sh1b + 64 * ST;        // 2 groups x 32 x ST
    float* sw1c = sh2b + 64 * ST;
    float* sb1c = sw1c + 128;
    float* sb2c = sb1c + 128;
    float* sb3c = sb2c + 128;
    float* sxb  = sb3c + 64;             // 2 groups x 32

    const int d    = blockIdx.y;
    const int tid  = threadIdx.x;
    const int g    = tid >> 8;           // group 0/1
    const int gtid = tid & 255;
    const int w8   = gtid >> 5, lane = gtid & 31;
    const int kl   = lane & 15, sg = lane >> 4;
    const int eh   = w8 & 1;             // output half
    const int rgw  = w8 >> 1;            // 0..3
    const int tr0  = rgw * 8 + sg * 4;   // rows 0..31 within group tile

    float* sh1 = sh1b + g * 32 * ST;
    float* sh2 = sh2b + g * 32 * ST;
    float* sx  = sxb + g * 32;
    const int bar = g + 1;

    for (int i = tid; i < HH * HH; i += 512) {
        int k = i >> 7, h = i & 127;
        sW2[k * ST + h] = w2[d * HH * HH + i];
    }
    for (int i = tid; i < EE * HH; i += 512) {
        int o = i >> 7, h = i & 127;
        sW3[o * ST + h] = w3[d * EE * HH + i];
    }
    if (tid < 128) {
        sw1c[tid] = w1[d * HH + tid];
        sb1c[tid] = b1[d * HH + tid];
        sb2c[tid] = b2[d * HH + tid];
    }
    if (tid < 64) sb3c[tid] = b3[d * EE + tid];
    __syncthreads();                     // weights staged; groups now diverge

    const int NT = BB / 32;              // 2048 tiles of 32 rows
    for (int t = blockIdx.x * 2 + g; t < NT; t += gridDim.x * 2) {
        const int r0 = t * 32;
        barg(bar);                       // prev tile fully consumed
        if (gtid < 32) sx[gtid] = x[(r0 + gtid) * DD + d];
        barg(bar);

        // sin1: 32 x 128 elements, 16 per thread
        #pragma unroll
        for (int i2 = 0; i2 < 16; i2++) {
            int i = gtid + 256 * i2;
            int r = i >> 7, h = i & 127;
            sh1[r * ST + h] = __sinf(fmaf(sx[r], sw1c[h], sb1c[h]));
        }
        barg(bar);

        // GEMM1: thread = 4 rows x 4 outs
        {
            ull acc[4][4];
            #pragma unroll
            for (int i = 0; i < 4; i++)
                #pragma unroll
                for (int s = 0; s < 4; s++) acc[i][s] = 0ull;

            const float* bp = sW2 + (kl + 64 * eh) * ST;
            const float* a0 = sh1 + tr0 * ST;
            #pragma unroll 2
            for (int h = 0; h < HH; h += 4) {
                ulonglong2 bv[4];
                #pragma unroll
                for (int s = 0; s < 4; s++) bv[s] = ld4(bp + s * 16 * ST + h);
                #pragma unroll
                for (int i = 0; i < 4; i++) {
                    ulonglong2 av = ld4(a0 + i * ST + h);
                    #pragma unroll
                    for (int s = 0; s < 4; s++) {
                        acc[i][s] = ffma2(av.x, bv[s].x, acc[i][s]);
                        acc[i][s] = ffma2(av.y, bv[s].y, acc[i][s]);
                    }
                }
            }
            #pragma unroll
            for (int i = 0; i < 4; i++)
                #pragma unroll
                for (int s = 0; s < 4; s++) {
                    float2 p = upk(acc[i][s]);
                    int k = kl + 16 * s + 64 * eh;
                    sh2[(tr0 + i) * ST + k] = __sinf(p.x + p.y + sb2c[k]);
                }
        }
        barg(bar);

        // GEMM2: thread = 4 rows x 2 outs
        {
            ull acc[4][2];
            #pragma unroll
            for (int i = 0; i < 4; i++)
                #pragma unroll
                for (int s = 0; s < 2; s++)
                    acc[i][s] = pk2(sb3c[kl + 16 * s + 32 * eh], 0.f);

            const float* bp = sW3 + (kl + 32 * eh) * ST;
            const float* a0 = sh2 + tr0 * ST;
            #pragma unroll 2
            for (int h = 0; h < HH; h += 4) {
                ulonglong2 bv[2];
                #pragma unroll
                for (int s = 0; s < 2; s++) bv[s] = ld4(bp + s * 16 * ST + h);
                #pragma unroll
                for (int i = 0; i < 4; i++) {
                    ulonglong2 av = ld4(a0 + i * ST + h);
                    #pragma unroll
                    for (int s = 0; s < 2; s++) {
                        acc[i][s] = ffma2(av.x, bv[s].x, acc[i][s]);
                        acc[i][s] = ffma2(av.y, bv[s].y, acc[i][s]);
                    }
                }
            }
            #pragma unroll
            for (int i = 0; i < 4; i++)
                #pragma unroll
                for (int s = 0; s < 2; s++) {
                    float2 p = upk(acc[i][s]);
                    int e = kl + 16 * s + 32 * eh;
                    g_tok[((r0 + tr0 + i) * DD + d) * EE + e] = p.x + p.y;
                }
        }
    }
}

// ============================================================================
// MHA (folded): tile 8 rows, cp.async double-buffered staging, shuffle pooling.
// (byte-identical to R13)
// ============================================================================
#define SW 68
#define SWT 68
#define SMH 68
#define MHA_PREFIX_F (128*SW + 128 + 4*SMH + 64 + 8 + 2*32*SW)   // 13528
#define MHA_SELF_F  (MHA_PREFIX_F + 2*32*SWT)   // 17880 (71.5 KB)
#define MHA_CROSS_F (MHA_PREFIX_F + 2*64*SWT)   // 22232 (88.9 KB)

template<int QOFF, int KVOFF, bool ACCUM, bool POOLB>
__global__ __launch_bounds__(256, 2)
void mha_kernel(const float* __restrict__ Win, const float* __restrict__ bin,
                const float* __restrict__ Wo,  const float* __restrict__ Wf)
{
    extern __shared__ float sm_[];
    float* sWqk  = sm_;                  // [e][c] e<64: Wq, e>=64: Wk
    float* sbqk  = sWqk + 128 * SW;      // 128
    float* smh   = sbqk + 128;           // [h][c]
    float* su    = smh + 4 * SMH;        // 64
    float* scb   = su + 64;              // 8
    float* sq    = scb + 8;              // [tr][68] (32 token-rows)
    float* sk    = sq + 32 * SW;
    float* stokA = sk + 32 * SW;         // buffer 0
    constexpr int SROWS = (QOFF == KVOFF) ? 32 : 64;
    float* stokB = stokA + SROWS * SWT;  // buffer 1

    const int tid  = threadIdx.x;
    const int w    = tid >> 5, lane = tid & 31;
    const int kl   = lane & 15, sg = lane >> 4;
    const int eh   = w & 1;              // 0 = Q, 1 = K
    const int rgw  = w >> 1;
    const int tr0  = rgw * 8 + sg * 4;

    constexpr bool SELF = (QOFF == KVOFF);
    constexpr int FOFF = POOLB ? 64 : 0;
    const int NT = BB / 8;

    for (int i = tid; i < 128 * 64; i += 256) {
        int e = i >> 6, c = i & 63;
        sWqk[e * SW + c] = Win[i];
    }
    if (tid < 128) sbqk[tid] = bin[tid];

    if (tid < 64) {
        float s = 0.f;
        for (int e = 0; e < 64; e++) s = fmaf(Wf[FOFF + e], Wo[e * 64 + tid], s);
        su[tid] = s;
    }
    __syncthreads();

    {
        int h = tid >> 6, dd2 = tid & 63;
        float s = 0.f;
        #pragma unroll
        for (int cc = 0; cc < 16; cc++)
            s = fmaf(su[h * 16 + cc], Win[(128 + h * 16 + cc) * 64 + dd2], s);
        smh[h * SMH + dd2] = s;
    }
    if (tid == 0) {
        float s = 0.f;
        for (int c = 0; c < 64; c++) s = fmaf(su[c], bin[128 + c], s);
        scb[0] = 0.5f * s;
    }

    auto issue = [&](int t, float* buf) {
        const int r0 = t * 8;
        if (SELF) {
            #pragma unroll
            for (int i2 = 0; i2 < 2; i2++) {
                int i = tid + 256 * i2;
                int trow = i >> 4, c4 = i & 15;
                int br = trow >> 2, tk = trow & 3;
                cpa16(buf + trow * SWT + c4 * 4,
                      g_tok + (r0 + br) * 512 + (QOFF + tk) * 64 + c4 * 4);
            }
        } else {
            #pragma unroll
            for (int i2 = 0; i2 < 4; i2++) {
                int i = tid + 256 * i2;
                int trow = i >> 4, c4 = i & 15;
                cpa16(buf + trow * SWT + c4 * 4, g_tok + r0 * 512 + i * 4);
            }
        }
    };

    if (blockIdx.x < NT) issue(blockIdx.x, stokA);
    CP_COMMIT();

    int parity = 0;
    for (int t = blockIdx.x; t < NT; t += gridDim.x) {
        const int r0 = t * 8;
        float* cur = parity ? stokB : stokA;
        float* nxt = parity ? stokA : stokB;

        __syncthreads();
        int tn = t + gridDim.x;
        if (tn < NT) issue(tn, nxt);
        CP_COMMIT();
        CP_WAIT1();
        __syncthreads();

        // ---- Q/K proj: thread = 4 token-rows x 4 outputs ------------------
        {
            ull acc[4][4];
            #pragma unroll
            for (int i = 0; i < 4; i++)
                #pragma unroll
                for (int s = 0; s < 4; s++)
                    acc[i][s] = pk2(sbqk[kl + 16 * s + 64 * eh], 0.f);

            const int off = eh ? KVOFF : QOFF;
            const float* ap[4];
            #pragma unroll
            for (int i = 0; i < 4; i++) {
                int tr = tr0 + i;
                int row;
                if (SELF) row = tr;
                else      row = (tr >> 2) * 8 + off + (tr & 3);
                ap[i] = cur + row * SWT;
            }
            const float* bp = sWqk + (kl + 64 * eh) * SW;

            #pragma unroll 2
            for (int c = 0; c < 64; c += 4) {
                ulonglong2 bv[4];
                #pragma unroll
                for (int s = 0; s < 4; s++) bv[s] = ld4(bp + s * 16 * SW + c);
                #pragma unroll
                for (int i = 0; i < 4; i++) {
                    ulonglong2 av = ld4(ap[i] + c);
                    #pragma unroll
                    for (int s = 0; s < 4; s++) {
                        acc[i][s] = ffma2(av.x, bv[s].x, acc[i][s]);
                        acc[i][s] = ffma2(av.y, bv[s].y, acc[i][s]);
                    }
                }
            }
            float* dest = eh ? sk : sq;
            #pragma unroll
            for (int i = 0; i < 4; i++) {
                int trw = (tr0 + i) * SW;
                #pragma unroll
                for (int s = 0; s < 4; s++) {
                    float2 p = upk(acc[i][s]);
                    dest[trw + kl + 16 * s] = p.x + p.y;
                }
            }
        }
        __syncthreads();

        // ---- attention + folded pooling: warp w -> batch row w ------------
        {
            const int br = w;
            const float* sq_r = sq + br * 4 * SW;
            const float* sk_r = sk + br * 4 * SW;

            float a01[2];
            #pragma unroll
            for (int z = 0; z < 2; z++) {
                int m = lane + 32 * z;
                int h = m >> 4, i = (m >> 2) & 3, j = m & 3;
                const float* qb = sq_r + i * SW + h * 16;
                const float* kb = sk_r + j * SW + h * 16;
                ull acc = 0ull;
                #pragma unroll
                for (int dd2 = 0; dd2 < 16; dd2 += 4) {
                    ulonglong2 qv = ld4(qb + dd2);
                    ulonglong2 kv = ld4(kb + dd2);
                    acc = ffma2(qv.x, kv.x, acc);
                    acc = ffma2(qv.y, kv.y, acc);
                }
                float2 p = upk(acc);
                a01[z] = (p.x + p.y) * 0.25f;
            }
            float m0 = a01[0], m1 = a01[1];
            m0 = fmaxf(m0, __shfl_xor_sync(0xffffffffu, m0, 1));
            m0 = fmaxf(m0, __shfl_xor_sync(0xffffffffu, m0, 2));
            m1 = fmaxf(m1, __shfl_xor_sync(0xffffffffu, m1, 1));
            m1 = fmaxf(m1, __shfl_xor_sync(0xffffffffu, m1, 2));
            float e0 = __expf(a01[0] - m0), e1 = __expf(a01[1] - m1);
            float s0 = e0, s1 = e1;
            s0 += __shfl_xor_sync(0xffffffffu, s0, 1);
            s0 += __shfl_xor_sync(0xffffffffu, s0, 2);
            s1 += __shfl_xor_sync(0xffffffffu, s1, 1);
            s1 += __shfl_xor_sync(0xffffffffu, s1, 2);
            float p0 = __fdividef(e0, s0);
            float p1 = __fdividef(e1, s1);

            float w0 = p0 + __shfl_xor_sync(0xffffffffu, p0, 4);
            w0 += __shfl_xor_sync(0xffffffffu, w0, 8);
            float w1 = p1 + __shfl_xor_sync(0xffffffffu, p1, 4);
            w1 += __shfl_xor_sync(0xffffffffu, w1, 8);

            int h = lane >> 2, j = lane & 3;
            int src = (h & 1) * 16 + j;
            float wa  = __shfl_sync(0xffffffffu, w0, src);
            float wbv = __shfl_sync(0xffffffffu, w1, src);
            float wbar = (h < 2) ? wa : wbv;

            float part = 0.f;
            {
                int kvrow = SELF ? (br * 4 + j) : (br * 8 + KVOFF + j);
                const float* mh = smh + h * SMH;
                const float* tj = cur + kvrow * SWT;
                ull acc = 0ull;
                #pragma unroll
                for (int c = 0; c < 64; c += 4) {
                    ulonglong2 mv = ld4(mh + c);
                    ulonglong2 tv = ld4(tj + c);
                    acc = ffma2(mv.x, tv.x, acc);
                    acc = ffma2(mv.y, tv.y, acc);
                }
                float2 p = upk(acc);
                part = wbar * (p.x + p.y);
                if (lane >= 16) part = 0.f;
            }
            part += __shfl_down_sync(0xffffffffu, part, 8);
            part += __shfl_down_sync(0xffffffffu, part, 4);
            part += __shfl_down_sync(0xffffffffu, part, 2);
            part += __shfl_down_sync(0xffffffffu, part, 1);
            if (lane == 0) {
                float S = 0.125f * part + scb[0];
                if (ACCUM) g_S[r0 + br] += S;
                else       g_S[r0 + br]  = S;
            }
        }
        parity ^= 1;
    }
}

// ---------------- epilogue: out = leaky(S + C) ------------------------------
__global__ __launch_bounds__(256)
void epi_kernel(const float* __restrict__ Wf, const float* __restrict__ bf,
                const float* __restrict__ bo_sa, const float* __restrict__ bo_sb,
                const float* __restrict__ bo_ca, const float* __restrict__ bo_cb,
                float* __restrict__ out)
{
    int b = blockIdx.x * blockDim.x + threadIdx.x;
    if (b >= BB) return;
    float C = bf[0];
    #pragma unroll 4
    for (int e = 0; e < 64; e++) {
        C = fmaf(0.5f * Wf[e],      bo_sa[e] + bo_ca[e], C);
        C = fmaf(0.5f * Wf[64 + e], bo_sb[e] + bo_cb[e], C);
    }
    float s = g_S[b] + C;
    out[b] = (s > 0.f) ? s : 0.01f * s;
}

// ---------------- launch ----------------------------------------------------
static const int A_SMEM   = TOK_SMEM_F * 4;
static const int M_SMEM_S = MHA_SELF_F * 4;
static const int M_SMEM_C = MHA_CROSS_F * 4;

extern "C" void kernel_launch(void* const* d_in, const int* in_sizes, int n_in,
                              void* d_out, int out_size)
{
    (void)in_sizes; (void)n_in; (void)out_size;
    const float* x  = (const float*)d_in[0];
    const float* w1 = (const float*)d_in[1];
    const float* b1 = (const float*)d_in[2];
    const float* w2 = (const float*)d_in[3];
    const float* b2 = (const float*)d_in[4];
    const float* w3 = (const float*)d_in[5];
    const float* b3 = (const float*)d_in[6];
    const float* Win_sa = (const float*)d_in[7];
    const float* bin_sa = (const float*)d_in[8];
    const float* Wo_sa  = (const float*)d_in[9];
    const float* bo_sa  = (const float*)d_in[10];
    const float* Win_sb = (const float*)d_in[11];
    const float* bin_sb = (const float*)d_in[12];
    const float* Wo_sb  = (const float*)d_in[13];
    const float* bo_sb  = (const float*)d_in[14];
    const float* Win_ca = (const float*)d_in[15];
    const float* bin_ca = (const float*)d_in[16];
    const float* Wo_ca  = (const float*)d_in[17];
    const float* bo_ca  = (const float*)d_in[18];
    const float* Win_cb = (const float*)d_in[19];
    const float* bin_cb = (const float*)d_in[20];
    const float* Wo_cb  = (const float*)d_in[21];
    const float* bo_cb  = (const float*)d_in[22];
    const float* Wf = (const float*)d_in[23];
    const float* bf = (const float*)d_in[24];
    float* out = (float*)d_out;

    cudaFuncSetAttribute(tok_kernel, cudaFuncAttributeMaxDynamicSharedMemorySize, A_SMEM);
    cudaFuncSetAttribute(mha_kernel<0, 0, false, false>, cudaFuncAttributeMaxDynamicSharedMemorySize, M_SMEM_S);
    cudaFuncSetAttribute(mha_kernel<4, 4, true,  true>,  cudaFuncAttributeMaxDynamicSharedMemorySize, M_SMEM_S);
    cudaFuncSetAttribute(mha_kernel<0, 4, true,  false>, cudaFuncAttributeMaxDynamicSharedMemorySize, M_SMEM_C);
    cudaFuncSetAttribute(mha_kernel<4, 0, true,  true>,  cudaFuncAttributeMaxDynamicSharedMemorySize, M_SMEM_C);

    tok_kernel<<<dim3(37, 8), 512, A_SMEM>>>(x, w1, b1, w2, b2, w3, b3);

    mha_kernel<0, 0, false, false><<<296, 256, M_SMEM_S>>>(Win_sa, bin_sa, Wo_sa, Wf);
    mha_kernel<4, 4, true,  true ><<<296, 256, M_SMEM_S>>>(Win_sb, bin_sb, Wo_sb, Wf);
    mha_kernel<0, 4, true,  false><<<296, 256, M_SMEM_C>>>(Win_ca, bin_ca, Wo_ca, Wf);
    mha_kernel<4, 0, true,  true ><<<296, 256, M_SMEM_C>>>(Win_cb, bin_cb, Wo_cb, Wf);

    epi_kernel<<<BB / 256, 256>>>(Wf, bf, bo_sa, bo_sb, bo_ca, bo_cb, out);
}